// round 3
// baseline (speedup 1.0000x reference)
#include <cuda_runtime.h>

#define N_NODES 100000
#define N_EDGES 1600000
#define N_GRAPH 1024
#define EMB 32
#define DC 128
#define WPB 8       // warps per block in node-parallel kernels
#define NTPB 256

// ---------------- scratch (static device globals; no allocation) ----------------
__device__ int   g_deg[N_NODES];
__device__ int   g_rowptr[N_NODES + 1];
__device__ int   g_cursor[N_NODES];
__device__ int   g_col[N_EDGES];
__device__ int   g_bsums[256];
__device__ int   g_boffs[256];
__device__ int   g_gdeg[N_GRAPH];
__device__ int   g_gptr[N_GRAPH + 1];
__device__ float g_xw[(size_t)N_NODES * DC];
__device__ float g_h1[(size_t)N_NODES * DC];
__device__ float g_als[N_NODES * 2];
__device__ float g_ald[N_NODES * 2];
__device__ float g_gate[N_NODES];

__device__ __forceinline__ float lrelu(float x, float s) { return x > 0.f ? x : s * x; }

// ---------------- CSR build ----------------
__global__ void k_zero() {
    int i = blockIdx.x * blockDim.x + threadIdx.x;
    if (i < N_NODES) g_deg[i] = 0;
    if (i < N_GRAPH) g_gdeg[i] = 0;
}

__global__ void k_hist(const int* __restrict__ ei, const int* __restrict__ batch) {
    int i = blockIdx.x * blockDim.x + threadIdx.x;
    if (i < N_EDGES) atomicAdd(&g_deg[ei[N_EDGES + i]], 1);
    if (i < N_NODES) atomicAdd(&g_gdeg[batch[i]], 1);
}

__global__ void k_scan_block(int which) {
    const int* in = which ? g_gdeg : g_deg;
    int* out = which ? g_gptr : g_rowptr;
    int n = which ? N_GRAPH : N_NODES;
    __shared__ int sh[1024];
    int t = threadIdx.x;
    int i = blockIdx.x * 1024 + t;
    int v = (i < n) ? in[i] : 0;
    sh[t] = v;
    __syncthreads();
    for (int off = 1; off < 1024; off <<= 1) {
        int a = (t >= off) ? sh[t - off] : 0;
        __syncthreads();
        sh[t] += a;
        __syncthreads();
    }
    if (i < n) out[i] = sh[t] - v;             // exclusive within block
    if (t == 1023) g_bsums[blockIdx.x] = sh[1023];
}

__global__ void k_scan_bsums(int which, int nb) {
    int* out = which ? g_gptr : g_rowptr;
    int n = which ? N_GRAPH : N_NODES;
    __shared__ int sh[128];
    int t = threadIdx.x;
    int v = (t < nb) ? g_bsums[t] : 0;
    sh[t] = v;
    __syncthreads();
    for (int off = 1; off < 128; off <<= 1) {
        int a = (t >= off) ? sh[t - off] : 0;
        __syncthreads();
        sh[t] += a;
        __syncthreads();
    }
    g_boffs[t] = sh[t] - v;                    // exclusive block offsets
    if (t == nb - 1) out[n] = sh[t];           // grand total
}

__global__ void k_scan_add(int which) {
    int n = which ? N_GRAPH : N_NODES;
    int* out = which ? g_gptr : g_rowptr;
    int i = blockIdx.x * blockDim.x + threadIdx.x;
    if (i < n) {
        int vv = out[i] + g_boffs[i >> 10];
        out[i] = vv;
        if (!which) g_cursor[i] = vv;
    }
}

__global__ void k_scatter(const int* __restrict__ ei) {
    int i = blockIdx.x * blockDim.x + threadIdx.x;
    if (i >= N_EDGES) return;
    int s = ei[i];
    int d = ei[N_EDGES + i];
    int pos = atomicAdd(&g_cursor[d], 1);
    g_col[pos] = s;
}

// deterministic order + gather locality: sort each row's src indices
__global__ void k_rowsort() {
    int n = blockIdx.x * blockDim.x + threadIdx.x;
    if (n >= N_NODES) return;
    int rs = g_rowptr[n], re = g_rowptr[n + 1];
    for (int i = rs + 1; i < re; i++) {
        int key = g_col[i];
        int j = i - 1;
        while (j >= rs && g_col[j] > key) { g_col[j + 1] = g_col[j]; j--; }
        g_col[j + 1] = key;
    }
}

// ---------------- layer 1 node transform: embed + LN + W1 + attention logits ----------------
__global__ void k_node1(const int* __restrict__ x, const float* __restrict__ emb,
                        const float* __restrict__ lng, const float* __restrict__ lnb,
                        const float* __restrict__ W1, const float* __restrict__ asr,
                        const float* __restrict__ adt) {
    __shared__ float4 sW[EMB * 32];  // W1 as [k][lane] float4
    int tid = threadIdx.x;
    const float4* W4 = (const float4*)W1;
    for (int i = tid; i < EMB * 32; i += blockDim.x) sW[i] = W4[i];
    __syncthreads();
    int n = blockIdx.x * WPB + (tid >> 5);
    int lane = tid & 31;
    if (n >= N_NODES) return;

    int vi = x[n];
    float xv = emb[vi * EMB + lane];
    float m = xv;
    for (int o = 16; o; o >>= 1) m += __shfl_xor_sync(~0u, m, o);
    m *= (1.f / EMB);
    float dv = xv - m;
    float var = dv * dv;
    for (int o = 16; o; o >>= 1) var += __shfl_xor_sync(~0u, var, o);
    var *= (1.f / EMB);
    float xn = dv * rsqrtf(var + 1e-5f) * lng[lane] + lnb[lane];

    float4 acc = make_float4(0.f, 0.f, 0.f, 0.f);
#pragma unroll
    for (int k = 0; k < EMB; k++) {
        float v = __shfl_sync(~0u, xn, k);
        float4 w = sW[k * 32 + lane];
        acc.x += v * w.x; acc.y += v * w.y; acc.z += v * w.z; acc.w += v * w.w;
    }
    ((float4*)g_xw)[(size_t)n * 32 + lane] = acc;

    float4 as = __ldg((const float4*)asr + lane);
    float4 ad = __ldg((const float4*)adt + lane);
    float ps = acc.x * as.x + acc.y * as.y + acc.z * as.z + acc.w * as.w;
    float pd = acc.x * ad.x + acc.y * ad.y + acc.z * ad.z + acc.w * ad.w;
    for (int o = 8; o; o >>= 1) {
        ps += __shfl_xor_sync(~0u, ps, o);
        pd += __shfl_xor_sync(~0u, pd, o);
    }
    if ((lane & 15) == 0) {
        int h = lane >> 4;
        g_als[n * 2 + h] = ps;
        g_ald[n * 2 + h] = pd;
    }
}

// ---------------- GAT aggregation: warp/node, online softmax, self-loop folded ----------------
__global__ void k_agg(const float* __restrict__ bias, float* __restrict__ out2, int layer) {
    int n = blockIdx.x * WPB + (threadIdx.x >> 5);
    int lane = threadIdx.x & 31;
    if (n >= N_NODES) return;

    int rs = g_rowptr[n], re = g_rowptr[n + 1];
    float ad0 = g_ald[2 * n], ad1 = g_ald[2 * n + 1];
    float as0 = g_als[2 * n], as1 = g_als[2 * n + 1];
    float e0 = lrelu(as0 + ad0, 0.2f), e1 = lrelu(as1 + ad1, 0.2f);
    float m = (lane < 16) ? e0 : e1;   // my head's running max (self-loop)
    float s = 1.f;                     // exp(e_self - m) = 1
    float4 acc = ((const float4*)g_xw)[(size_t)n * 32 + lane];  // xw[n] * 1

    for (int k = rs; k < re; k++) {
        int src = g_col[k];
        float2 av = *(const float2*)(g_als + 2 * src);
        float f0 = lrelu(av.x + ad0, 0.2f);
        float f1 = lrelu(av.y + ad1, 0.2f);
        float e = (lane < 16) ? f0 : f1;
        float4 xv = ((const float4*)g_xw)[(size_t)src * 32 + lane];
        float mn = fmaxf(m, e);
        float sc = __expf(m - mn);
        float p = __expf(e - mn);
        s = s * sc + p;
        acc.x = acc.x * sc + xv.x * p;
        acc.y = acc.y * sc + xv.y * p;
        acc.z = acc.z * sc + xv.z * p;
        acc.w = acc.w * sc + xv.w * p;
        m = mn;
    }
    float inv = 1.f / s;
    float4 b = __ldg((const float4*)bias + lane);
    float4 o;
    o.x = acc.x * inv + b.x;
    o.y = acc.y * inv + b.y;
    o.z = acc.z * inv + b.z;
    o.w = acc.w * inv + b.w;
    if (layer == 1) {
        o.x = lrelu(o.x, 0.05f); o.y = lrelu(o.y, 0.05f);
        o.z = lrelu(o.z, 0.05f); o.w = lrelu(o.w, 0.05f);
        ((float4*)g_h1)[(size_t)n * 32 + lane] = o;
    } else {
        ((float4*)out2)[(size_t)n * 32 + lane] = o;
    }
}

// ---------------- layer 2 node transform: h1 @ W2 + attention logits ----------------
__global__ void k_node2(const float* __restrict__ W2, const float* __restrict__ asr,
                        const float* __restrict__ adt) {
    __shared__ float4 shrow[WPB * 32];
    int wl = threadIdx.x >> 5;
    int lane = threadIdx.x & 31;
    int n = blockIdx.x * WPB + wl;
    if (n >= N_NODES) return;

    float4 hv = ((const float4*)g_h1)[(size_t)n * 32 + lane];
    shrow[wl * 32 + lane] = hv;
    __syncwarp();
    const float* hr = (const float*)(shrow + wl * 32);
    const float4* W4 = (const float4*)W2;
    float4 acc = make_float4(0.f, 0.f, 0.f, 0.f);
#pragma unroll 8
    for (int k = 0; k < DC; k += 4) {
        float4 h4 = *(const float4*)(hr + k);
        float4 w;
        w = __ldg(W4 + (k + 0) * 32 + lane);
        acc.x += h4.x * w.x; acc.y += h4.x * w.y; acc.z += h4.x * w.z; acc.w += h4.x * w.w;
        w = __ldg(W4 + (k + 1) * 32 + lane);
        acc.x += h4.y * w.x; acc.y += h4.y * w.y; acc.z += h4.y * w.z; acc.w += h4.y * w.w;
        w = __ldg(W4 + (k + 2) * 32 + lane);
        acc.x += h4.z * w.x; acc.y += h4.z * w.y; acc.z += h4.z * w.z; acc.w += h4.z * w.w;
        w = __ldg(W4 + (k + 3) * 32 + lane);
        acc.x += h4.w * w.x; acc.y += h4.w * w.y; acc.z += h4.w * w.z; acc.w += h4.w * w.w;
    }
    ((float4*)g_xw)[(size_t)n * 32 + lane] = acc;

    float4 as = __ldg((const float4*)asr + lane);
    float4 ad = __ldg((const float4*)adt + lane);
    float ps = acc.x * as.x + acc.y * as.y + acc.z * as.z + acc.w * as.w;
    float pd = acc.x * ad.x + acc.y * ad.y + acc.z * ad.z + acc.w * ad.w;
    for (int o = 8; o; o >>= 1) {
        ps += __shfl_xor_sync(~0u, ps, o);
        pd += __shfl_xor_sync(~0u, pd, o);
    }
    if ((lane & 15) == 0) {
        int h = lane >> 4;
        g_als[n * 2 + h] = ps;
        g_ald[n * 2 + h] = pd;
    }
}

// ---------------- gate MLP ----------------
__global__ void k_gate(const float* __restrict__ hout, const float* __restrict__ gw1,
                       const float* __restrict__ gb1, const float* __restrict__ gw2,
                       const float* __restrict__ gb2) {
    __shared__ float sg1[DC * 64];        // 32 KB
    __shared__ float4 shrow[WPB * 32];
    for (int i = threadIdx.x; i < DC * 64; i += blockDim.x) sg1[i] = gw1[i];
    __syncthreads();
    int wl = threadIdx.x >> 5;
    int lane = threadIdx.x & 31;
    int n = blockIdx.x * WPB + wl;
    if (n >= N_NODES) return;

    float4 hv = ((const float4*)hout)[(size_t)n * 32 + lane];
    shrow[wl * 32 + lane] = hv;
    __syncwarp();
    const float* hr = (const float*)(shrow + wl * 32);
    float u0 = 0.f, u1 = 0.f;
#pragma unroll 8
    for (int k = 0; k < DC; k++) {
        float hk = hr[k];
        float2 w = *(const float2*)(sg1 + k * 64 + lane * 2);
        u0 += hk * w.x;
        u1 += hk * w.y;
    }
    u0 = lrelu(u0 + __ldg(gb1 + lane * 2), 0.05f);
    u1 = lrelu(u1 + __ldg(gb1 + lane * 2 + 1), 0.05f);
    float ps = u0 * __ldg(gw2 + lane * 2) + u1 * __ldg(gw2 + lane * 2 + 1);
    for (int o = 16; o; o >>= 1) ps += __shfl_xor_sync(~0u, ps, o);
    if (lane == 0) g_gate[n] = ps + __ldg(gb2);
}

// ---------------- per-graph softmax pooling (batch_idx sorted -> contiguous segments) ----------------
__global__ void k_pool(const float* __restrict__ hout, float* __restrict__ zout) {
    int g = blockIdx.x;
    int t = threadIdx.x;
    int s = g_gptr[g], e = g_gptr[g + 1];
    __shared__ float red[128];
    __shared__ float wbuf[128];

    float lm = -3.4e38f;
    for (int i = s + t; i < e; i += 128) lm = fmaxf(lm, g_gate[i]);
    red[t] = lm;
    __syncthreads();
    for (int o = 64; o; o >>= 1) { if (t < o) red[t] = fmaxf(red[t], red[t + o]); __syncthreads(); }
    float gm = red[0];
    __syncthreads();

    float ls = 0.f;
    for (int i = s + t; i < e; i += 128) ls += __expf(g_gate[i] - gm);
    red[t] = ls;
    __syncthreads();
    for (int o = 64; o; o >>= 1) { if (t < o) red[t] += red[t + o]; __syncthreads(); }
    float inv = (e > s) ? 1.f / red[0] : 0.f;
    __syncthreads();

    float acc = 0.f;
    for (int base = s; base < e; base += 128) {
        int i = base + t;
        wbuf[t] = (i < e) ? __expf(g_gate[i] - gm) * inv : 0.f;
        __syncthreads();
        int cnt = min(128, e - base);
        for (int j = 0; j < cnt; j++)
            acc += wbuf[j] * hout[(size_t)(base + j) * DC + t];
        __syncthreads();
    }
    zout[g * DC + t] = acc;
}

// ---------------- launch ----------------
extern "C" void kernel_launch(void* const* d_in, const int* in_sizes, int n_in,
                              void* d_out, int out_size) {
    const int*   x     = (const int*)d_in[0];
    const int*   ei    = (const int*)d_in[1];
    const int*   batch = (const int*)d_in[2];
    const float* emb   = (const float*)d_in[3];
    const float* lng   = (const float*)d_in[4];
    const float* lnb   = (const float*)d_in[5];
    const float* W1    = (const float*)d_in[6];
    const float* as1   = (const float*)d_in[7];
    const float* ad1   = (const float*)d_in[8];
    const float* b1    = (const float*)d_in[9];
    const float* W2    = (const float*)d_in[10];
    const float* as2   = (const float*)d_in[11];
    const float* ad2   = (const float*)d_in[12];
    const float* b2    = (const float*)d_in[13];
    const float* gw1   = (const float*)d_in[14];
    const float* gb1   = (const float*)d_in[15];
    const float* gw2   = (const float*)d_in[16];
    const float* gb2   = (const float*)d_in[17];
    float* out  = (float*)d_out;
    float* zout = out + (size_t)N_NODES * DC;

    // CSR build (reused by both GAT layers) + graph segment pointers
    k_zero<<<(N_NODES + 255) / 256, 256>>>();
    k_hist<<<(N_EDGES + 255) / 256, 256>>>(ei, batch);
    k_scan_block<<<(N_NODES + 1023) / 1024, 1024>>>(0);
    k_scan_bsums<<<1, 128>>>(0, (N_NODES + 1023) / 1024);
    k_scan_add<<<(N_NODES + 255) / 256, 256>>>(0);
    k_scatter<<<(N_EDGES + 255) / 256, 256>>>(ei);
    k_rowsort<<<(N_NODES + 255) / 256, 256>>>();
    k_scan_block<<<1, 1024>>>(1);
    k_scan_bsums<<<1, 128>>>(1, 1);
    k_scan_add<<<(N_GRAPH + 255) / 256, 256>>>(1);

    int nb = (N_NODES + WPB - 1) / WPB;
    k_node1<<<nb, NTPB>>>(x, emb, lng, lnb, W1, as1, ad1);
    k_agg<<<nb, NTPB>>>(b1, nullptr, 1);
    k_node2<<<nb, NTPB>>>(W2, as2, ad2);
    k_agg<<<nb, NTPB>>>(b2, out, 2);
    k_gate<<<nb, NTPB>>>(out, gw1, gb1, gw2, gb2);
    k_pool<<<N_GRAPH, 128>>>(out, zout);
}

// round 4
// speedup vs baseline: 1.5532x; 1.5532x over previous
#include <cuda_runtime.h>

#define N_NODES 100000
#define N_EDGES 1600000
#define N_GRAPH 1024
#define EMB 32
#define DC 128
#define WPB 8       // warps per block
#define NPW 8       // nodes per warp (register blocking in dense kernels)
#define NTPB 256

// ---------------- scratch (static device globals; no allocation) ----------------
__device__ int   g_deg[N_NODES];
__device__ int   g_rowptr[N_NODES + 1];
__device__ int   g_cursor[N_NODES];
__device__ int   g_col[N_EDGES];
__device__ int   g_dst[N_EDGES];
__device__ int   g_bsums[256];
__device__ int   g_boffs[256];
__device__ int   g_gdeg[N_GRAPH];
__device__ int   g_gptr[N_GRAPH + 1];
__device__ float g_xw[(size_t)N_NODES * DC];
__device__ float g_h1[(size_t)N_NODES * DC];
__device__ float g_als[N_NODES * 2];
__device__ float g_ald[N_NODES * 2];
__device__ float g_elog[(size_t)N_EDGES * 2];
__device__ float g_gate[N_NODES];

__device__ __forceinline__ float lrelu(float x, float s) { return x > 0.f ? x : s * x; }

// f32x2 packed helpers (sm_103a; ptxas never emits FFMA2 from C++)
__device__ __forceinline__ unsigned long long pack2(float v) {
    unsigned long long r; asm("mov.b64 %0,{%1,%1};" : "=l"(r) : "f"(v)); return r;
}
__device__ __forceinline__ void fma2(unsigned long long& a, unsigned long long x, unsigned long long p) {
    asm("fma.rn.f32x2 %0,%1,%2,%0;" : "+l"(a) : "l"(x), "l"(p));
}
__device__ __forceinline__ float2 unpack2(unsigned long long v) {
    float2 r; asm("mov.b64 {%0,%1},%2;" : "=f"(r.x), "=f"(r.y) : "l"(v)); return r;
}

// ---------------- CSR build ----------------
__global__ void k_zero() {
    int i = blockIdx.x * blockDim.x + threadIdx.x;
    if (i < N_NODES) g_deg[i] = 0;
    if (i < N_GRAPH) g_gdeg[i] = 0;
}

__global__ void k_hist(const int* __restrict__ ei, const int* __restrict__ batch) {
    int i = blockIdx.x * blockDim.x + threadIdx.x;
    if (i < N_EDGES) atomicAdd(&g_deg[ei[N_EDGES + i]], 1);
    if (i < N_NODES) atomicAdd(&g_gdeg[batch[i]], 1);
}

__global__ void k_scan_block(int which) {
    const int* in = which ? g_gdeg : g_deg;
    int* out = which ? g_gptr : g_rowptr;
    int n = which ? N_GRAPH : N_NODES;
    __shared__ int sh[1024];
    int t = threadIdx.x;
    int i = blockIdx.x * 1024 + t;
    int v = (i < n) ? in[i] : 0;
    sh[t] = v;
    __syncthreads();
    for (int off = 1; off < 1024; off <<= 1) {
        int a = (t >= off) ? sh[t - off] : 0;
        __syncthreads();
        sh[t] += a;
        __syncthreads();
    }
    if (i < n) out[i] = sh[t] - v;
    if (t == 1023) g_bsums[blockIdx.x] = sh[1023];
}

__global__ void k_scan_bsums(int which, int nb) {
    int* out = which ? g_gptr : g_rowptr;
    int n = which ? N_GRAPH : N_NODES;
    __shared__ int sh[128];
    int t = threadIdx.x;
    int v = (t < nb) ? g_bsums[t] : 0;
    sh[t] = v;
    __syncthreads();
    for (int off = 1; off < 128; off <<= 1) {
        int a = (t >= off) ? sh[t - off] : 0;
        __syncthreads();
        sh[t] += a;
        __syncthreads();
    }
    g_boffs[t] = sh[t] - v;
    if (t == nb - 1) out[n] = sh[t];
}

__global__ void k_scan_add(int which) {
    int n = which ? N_GRAPH : N_NODES;
    int* out = which ? g_gptr : g_rowptr;
    int i = blockIdx.x * blockDim.x + threadIdx.x;
    if (i < n) {
        int vv = out[i] + g_boffs[i >> 10];
        out[i] = vv;
        if (!which) g_cursor[i] = vv;
    }
}

__global__ void k_scatter(const int* __restrict__ ei) {
    int i = blockIdx.x * blockDim.x + threadIdx.x;
    if (i >= N_EDGES) return;
    int s = ei[i];
    int d = ei[N_EDGES + i];
    int pos = atomicAdd(&g_cursor[d], 1);
    g_col[pos] = s;
    g_dst[pos] = d;
}

// warp-per-node smem odd-even sort (deterministic edge order + gather locality)
__global__ void k_rowsortw() {
    __shared__ int buf[WPB][160];
    int wl = threadIdx.x >> 5, lane = threadIdx.x & 31;
    int n = blockIdx.x * WPB + wl;
    if (n >= N_NODES) return;
    int rs = g_rowptr[n], L = g_rowptr[n + 1] - rs;
    if (L <= 1) return;
    if (L <= 160) {
        for (int i = lane; i < L; i += 32) buf[wl][i] = g_col[rs + i];
        __syncwarp();
        for (int p = 0; p < L; p++) {
            for (int i = (p & 1) + 2 * lane; i + 1 < L; i += 64) {
                int a = buf[wl][i], b = buf[wl][i + 1];
                if (a > b) { buf[wl][i] = b; buf[wl][i + 1] = a; }
            }
            __syncwarp();
        }
        for (int i = lane; i < L; i += 32) g_col[rs + i] = buf[wl][i];
    } else if (lane == 0) {
        int re = rs + L;
        for (int i = rs + 1; i < re; i++) {
            int key = g_col[i];
            int j = i - 1;
            while (j >= rs && g_col[j] > key) { g_col[j + 1] = g_col[j]; j--; }
            g_col[j + 1] = key;
        }
    }
}

// ---------------- layer 1: embed + LN + W1 + logits (8 nodes/warp, f32x2) ----------------
__global__ void k_node1(const int* __restrict__ x, const float* __restrict__ emb,
                        const float* __restrict__ lng, const float* __restrict__ lnb,
                        const float* __restrict__ W1, const float* __restrict__ asr,
                        const float* __restrict__ adt) {
    __shared__ ulonglong2 sW[EMB * 32];          // 16KB: W1 [k][lane] as 4 floats
    __shared__ float sxn[WPB][NPW][EMB];         // 8KB
    int tid = threadIdx.x;
    int wl = tid >> 5, lane = tid & 31;
    {
        const ulonglong2* W4 = (const ulonglong2*)W1;
        for (int i = tid; i < EMB * 32; i += NTPB) sW[i] = W4[i];
    }
    int nbase = (blockIdx.x * WPB + wl) * NPW;

    // stage A: LayerNorm rows
#pragma unroll
    for (int j = 0; j < NPW; j++) {
        int n = nbase + j;
        float xn = 0.f;
        if (n < N_NODES) {
            int vi = x[n];
            float xv = emb[vi * EMB + lane];
            float m = xv;
            for (int o = 16; o; o >>= 1) m += __shfl_xor_sync(~0u, m, o);
            m *= (1.f / EMB);
            float dv = xv - m;
            float var = dv * dv;
            for (int o = 16; o; o >>= 1) var += __shfl_xor_sync(~0u, var, o);
            var *= (1.f / EMB);
            xn = dv * rsqrtf(var + 1e-5f) * lng[lane] + lnb[lane];
        }
        sxn[wl][j][lane] = xn;
    }
    __syncthreads();   // sW visibility (covers stage A warp-local too)

    // stage B: blocked matmul
    unsigned long long accA[NPW], accB[NPW];
#pragma unroll
    for (int j = 0; j < NPW; j++) { accA[j] = 0ull; accB[j] = 0ull; }
#pragma unroll
    for (int k = 0; k < EMB; k += 4) {
        ulonglong2 w0 = sW[(k + 0) * 32 + lane];
        ulonglong2 w1 = sW[(k + 1) * 32 + lane];
        ulonglong2 w2 = sW[(k + 2) * 32 + lane];
        ulonglong2 w3 = sW[(k + 3) * 32 + lane];
#pragma unroll
        for (int j = 0; j < NPW; j++) {
            float4 h4 = *(const float4*)&sxn[wl][j][k];
            unsigned long long p;
            p = pack2(h4.x); fma2(accA[j], w0.x, p); fma2(accB[j], w0.y, p);
            p = pack2(h4.y); fma2(accA[j], w1.x, p); fma2(accB[j], w1.y, p);
            p = pack2(h4.z); fma2(accA[j], w2.x, p); fma2(accB[j], w2.y, p);
            p = pack2(h4.w); fma2(accA[j], w3.x, p); fma2(accB[j], w3.y, p);
        }
    }

    float4 as4 = __ldg((const float4*)asr + lane);
    float4 ad4 = __ldg((const float4*)adt + lane);
#pragma unroll
    for (int j = 0; j < NPW; j++) {
        int n = nbase + j;
        float2 lo = unpack2(accA[j]), hi = unpack2(accB[j]);
        float ps = lo.x * as4.x + lo.y * as4.y + hi.x * as4.z + hi.y * as4.w;
        float pd = lo.x * ad4.x + lo.y * ad4.y + hi.x * ad4.z + hi.y * ad4.w;
        for (int o = 8; o; o >>= 1) {
            ps += __shfl_xor_sync(~0u, ps, o);
            pd += __shfl_xor_sync(~0u, pd, o);
        }
        if (n < N_NODES) {
            ((float4*)g_xw)[(size_t)n * 32 + lane] = make_float4(lo.x, lo.y, hi.x, hi.y);
            if ((lane & 15) == 0) {
                int h = lane >> 4;
                g_als[n * 2 + h] = ps;
                g_ald[n * 2 + h] = pd;
            }
        }
    }
}

// ---------------- edge-parallel logit precompute ----------------
__global__ void k_elog() {
    int p = blockIdx.x * blockDim.x + threadIdx.x;
    if (p >= N_EDGES) return;
    int s = g_col[p], d = g_dst[p];
    float2 a = *(const float2*)&g_als[2 * s];
    float2 b = *(const float2*)&g_ald[2 * d];
    ((float2*)g_elog)[p] = make_float2(lrelu(a.x + b.x, 0.2f), lrelu(a.y + b.y, 0.2f));
}

// ---------------- GAT aggregation: warp/node, two-pass softmax, f32x2 ----------------
__global__ void k_agg(const float* __restrict__ bias, float* __restrict__ out2, int layer) {
    int n = blockIdx.x * WPB + (threadIdx.x >> 5);
    int lane = threadIdx.x & 31;
    if (n >= N_NODES) return;
    int head = lane >> 4, sub = lane & 15;

    int rs = g_rowptr[n], re = g_rowptr[n + 1];
    float2 a = *(const float2*)&g_als[2 * n];
    float2 b = *(const float2*)&g_ald[2 * n];
    float eself = head ? lrelu(a.y + b.y, 0.2f) : lrelu(a.x + b.x, 0.2f);

    // pass 1: max per head (half-warp cooperative over contiguous elog)
    float m = eself;
    for (int k = rs + sub; k < re; k += 16) {
        float2 e2 = __ldg((const float2*)g_elog + k);
        m = fmaxf(m, head ? e2.y : e2.x);
    }
    for (int o = 8; o; o >>= 1) m = fmaxf(m, __shfl_xor_sync(~0u, m, o));

    // pass 2: sum of exp
    float s = 0.f;
    for (int k = rs + sub; k < re; k += 16) {
        float2 e2 = __ldg((const float2*)g_elog + k);
        s += __expf((head ? e2.y : e2.x) - m);
    }
    for (int o = 8; o; o >>= 1) s += __shfl_xor_sync(~0u, s, o);
    float pself = __expf(eself - m);
    s += pself;
    float inv = 1.f / s;

    // pass 3: weighted feature accumulation (no rescale recurrence)
    ulonglong2 xs = __ldg((const ulonglong2*)g_xw + (size_t)n * 32 + lane);
    unsigned long long acc0, acc1;
    {
        unsigned long long p2 = pack2(pself);
        asm("mul.rn.f32x2 %0,%1,%2;" : "=l"(acc0) : "l"(xs.x), "l"(p2));
        asm("mul.rn.f32x2 %0,%1,%2;" : "=l"(acc1) : "l"(xs.y), "l"(p2));
    }
#pragma unroll 4
    for (int k = rs; k < re; k++) {
        int src = __ldg(g_col + k);
        float2 e2 = __ldg((const float2*)g_elog + k);
        float p = __expf((head ? e2.y : e2.x) - m);
        ulonglong2 xv = __ldg((const ulonglong2*)g_xw + (size_t)src * 32 + lane);
        unsigned long long p2 = pack2(p);
        fma2(acc0, xv.x, p2);
        fma2(acc1, xv.y, p2);
    }

    float2 lo = unpack2(acc0), hi = unpack2(acc1);
    float4 bi = __ldg((const float4*)bias + lane);
    float4 o;
    o.x = lo.x * inv + bi.x;
    o.y = lo.y * inv + bi.y;
    o.z = hi.x * inv + bi.z;
    o.w = hi.y * inv + bi.w;
    if (layer == 1) {
        o.x = lrelu(o.x, 0.05f); o.y = lrelu(o.y, 0.05f);
        o.z = lrelu(o.z, 0.05f); o.w = lrelu(o.w, 0.05f);
        ((float4*)g_h1)[(size_t)n * 32 + lane] = o;
    } else {
        ((float4*)out2)[(size_t)n * 32 + lane] = o;
    }
}

// ---------------- layer 2 node transform: h1 @ W2 + logits (8 nodes/warp, smem W2) ----------------
__global__ void k_node2(const float* __restrict__ W2, const float* __restrict__ asr,
                        const float* __restrict__ adt) {
    extern __shared__ float dsm[];
    ulonglong2* sW = (ulonglong2*)dsm;                 // DC*32 entries = 64KB
    float* sh = dsm + DC * DC;                         // WPB*NPW*DC floats = 16KB
    int tid = threadIdx.x;
    int wl = tid >> 5, lane = tid & 31;
    {
        const ulonglong2* W4 = (const ulonglong2*)W2;
        for (int i = tid; i < DC * 32; i += NTPB) sW[i] = W4[i];
    }
    int nbase = (blockIdx.x * WPB + wl) * NPW;
    float* shw = sh + (size_t)wl * NPW * DC;
#pragma unroll
    for (int j = 0; j < NPW; j++) {
        int n = nbase + j;
        float4 v = (n < N_NODES) ? ((const float4*)g_h1)[(size_t)n * 32 + lane]
                                 : make_float4(0.f, 0.f, 0.f, 0.f);
        *(float4*)&shw[j * DC + lane * 4] = v;
    }
    __syncthreads();

    unsigned long long accA[NPW], accB[NPW];
#pragma unroll
    for (int j = 0; j < NPW; j++) { accA[j] = 0ull; accB[j] = 0ull; }
    for (int k = 0; k < DC; k += 4) {
        ulonglong2 w0 = sW[(k + 0) * 32 + lane];
        ulonglong2 w1 = sW[(k + 1) * 32 + lane];
        ulonglong2 w2 = sW[(k + 2) * 32 + lane];
        ulonglong2 w3 = sW[(k + 3) * 32 + lane];
#pragma unroll
        for (int j = 0; j < NPW; j++) {
            float4 h4 = *(const float4*)&shw[j * DC + k];
            unsigned long long p;
            p = pack2(h4.x); fma2(accA[j], w0.x, p); fma2(accB[j], w0.y, p);
            p = pack2(h4.y); fma2(accA[j], w1.x, p); fma2(accB[j], w1.y, p);
            p = pack2(h4.z); fma2(accA[j], w2.x, p); fma2(accB[j], w2.y, p);
            p = pack2(h4.w); fma2(accA[j], w3.x, p); fma2(accB[j], w3.y, p);
        }
    }

    float4 as4 = __ldg((const float4*)asr + lane);
    float4 ad4 = __ldg((const float4*)adt + lane);
#pragma unroll
    for (int j = 0; j < NPW; j++) {
        int n = nbase + j;
        float2 lo = unpack2(accA[j]), hi = unpack2(accB[j]);
        float ps = lo.x * as4.x + lo.y * as4.y + hi.x * as4.z + hi.y * as4.w;
        float pd = lo.x * ad4.x + lo.y * ad4.y + hi.x * ad4.z + hi.y * ad4.w;
        for (int o = 8; o; o >>= 1) {
            ps += __shfl_xor_sync(~0u, ps, o);
            pd += __shfl_xor_sync(~0u, pd, o);
        }
        if (n < N_NODES) {
            ((float4*)g_xw)[(size_t)n * 32 + lane] = make_float4(lo.x, lo.y, hi.x, hi.y);
            if ((lane & 15) == 0) {
                int h = lane >> 4;
                g_als[n * 2 + h] = ps;
                g_ald[n * 2 + h] = pd;
            }
        }
    }
}

// ---------------- gate MLP (8 nodes/warp, smem gw1) ----------------
__global__ void k_gate(const float* __restrict__ hout, const float* __restrict__ gw1,
                       const float* __restrict__ gb1, const float* __restrict__ gw2,
                       const float* __restrict__ gb2) {
    extern __shared__ float dsm[];
    unsigned long long* sg = (unsigned long long*)dsm;   // DC*32 entries (float2 pairs), 32KB
    float* sh = dsm + DC * 64;                           // stage 16KB
    int tid = threadIdx.x;
    int wl = tid >> 5, lane = tid & 31;
    {
        const unsigned long long* G = (const unsigned long long*)gw1;
        for (int i = tid; i < DC * 32; i += NTPB) sg[i] = G[i];
    }
    int nbase = (blockIdx.x * WPB + wl) * NPW;
    float* shw = sh + (size_t)wl * NPW * DC;
#pragma unroll
    for (int j = 0; j < NPW; j++) {
        int n = nbase + j;
        float4 v = (n < N_NODES) ? ((const float4*)hout)[(size_t)n * 32 + lane]
                                 : make_float4(0.f, 0.f, 0.f, 0.f);
        *(float4*)&shw[j * DC + lane * 4] = v;
    }
    __syncthreads();

    unsigned long long acc[NPW];
#pragma unroll
    for (int j = 0; j < NPW; j++) acc[j] = 0ull;
    for (int k = 0; k < DC; k += 4) {
        unsigned long long w0 = sg[(k + 0) * 32 + lane];
        unsigned long long w1 = sg[(k + 1) * 32 + lane];
        unsigned long long w2 = sg[(k + 2) * 32 + lane];
        unsigned long long w3 = sg[(k + 3) * 32 + lane];
#pragma unroll
        for (int j = 0; j < NPW; j++) {
            float4 h4 = *(const float4*)&shw[j * DC + k];
            fma2(acc[j], w0, pack2(h4.x));
            fma2(acc[j], w1, pack2(h4.y));
            fma2(acc[j], w2, pack2(h4.z));
            fma2(acc[j], w3, pack2(h4.w));
        }
    }

    float2 gb = __ldg((const float2*)gb1 + lane);
    float2 g2 = __ldg((const float2*)gw2 + lane);
    float gbias = __ldg(gb2);
#pragma unroll
    for (int j = 0; j < NPW; j++) {
        float2 u = unpack2(acc[j]);
        u.x = lrelu(u.x + gb.x, 0.05f);
        u.y = lrelu(u.y + gb.y, 0.05f);
        float ps = u.x * g2.x + u.y * g2.y;
        for (int o = 16; o; o >>= 1) ps += __shfl_xor_sync(~0u, ps, o);
        int n = nbase + j;
        if (lane == 0 && n < N_NODES) g_gate[n] = ps + gbias;
    }
}

// ---------------- per-graph softmax pooling ----------------
__global__ void k_pool(const float* __restrict__ hout, float* __restrict__ zout) {
    int g = blockIdx.x;
    int t = threadIdx.x;
    int s = g_gptr[g], e = g_gptr[g + 1];
    __shared__ float red[128];
    __shared__ float wbuf[128];

    float lm = -3.4e38f;
    for (int i = s + t; i < e; i += 128) lm = fmaxf(lm, g_gate[i]);
    red[t] = lm;
    __syncthreads();
    for (int o = 64; o; o >>= 1) { if (t < o) red[t] = fmaxf(red[t], red[t + o]); __syncthreads(); }
    float gm = red[0];
    __syncthreads();

    float ls = 0.f;
    for (int i = s + t; i < e; i += 128) ls += __expf(g_gate[i] - gm);
    red[t] = ls;
    __syncthreads();
    for (int o = 64; o; o >>= 1) { if (t < o) red[t] += red[t + o]; __syncthreads(); }
    float inv = (e > s) ? 1.f / red[0] : 0.f;
    __syncthreads();

    float acc = 0.f;
    for (int base = s; base < e; base += 128) {
        int i = base + t;
        wbuf[t] = (i < e) ? __expf(g_gate[i] - gm) * inv : 0.f;
        __syncthreads();
        int cnt = min(128, e - base);
        for (int j = 0; j < cnt; j++)
            acc += wbuf[j] * hout[(size_t)(base + j) * DC + t];
        __syncthreads();
    }
    zout[g * DC + t] = acc;
}

// ---------------- launch ----------------
extern "C" void kernel_launch(void* const* d_in, const int* in_sizes, int n_in,
                              void* d_out, int out_size) {
    const int*   x     = (const int*)d_in[0];
    const int*   ei    = (const int*)d_in[1];
    const int*   batch = (const int*)d_in[2];
    const float* emb   = (const float*)d_in[3];
    const float* lng   = (const float*)d_in[4];
    const float* lnb   = (const float*)d_in[5];
    const float* W1    = (const float*)d_in[6];
    const float* as1   = (const float*)d_in[7];
    const float* ad1   = (const float*)d_in[8];
    const float* b1    = (const float*)d_in[9];
    const float* W2    = (const float*)d_in[10];
    const float* as2   = (const float*)d_in[11];
    const float* ad2   = (const float*)d_in[12];
    const float* b2    = (const float*)d_in[13];
    const float* gw1   = (const float*)d_in[14];
    const float* gb1   = (const float*)d_in[15];
    const float* gw2   = (const float*)d_in[16];
    const float* gb2   = (const float*)d_in[17];
    float* out  = (float*)d_out;
    float* zout = out + (size_t)N_NODES * DC;

    const int node2_smem = DC * DC * 4 + WPB * NPW * DC * 4;   // 80 KB
    const int gate_smem  = DC * 64 * 4 + WPB * NPW * DC * 4;   // 48 KB
    cudaFuncSetAttribute(k_node2, cudaFuncAttributeMaxDynamicSharedMemorySize, node2_smem);
    cudaFuncSetAttribute(k_gate,  cudaFuncAttributeMaxDynamicSharedMemorySize, gate_smem);

    // CSR build + graph segment pointers
    k_zero<<<(N_NODES + 255) / 256, 256>>>();
    k_hist<<<(N_EDGES + 255) / 256, 256>>>(ei, batch);
    k_scan_block<<<(N_NODES + 1023) / 1024, 1024>>>(0);
    k_scan_bsums<<<1, 128>>>(0, (N_NODES + 1023) / 1024);
    k_scan_add<<<(N_NODES + 255) / 256, 256>>>(0);
    k_scatter<<<(N_EDGES + 255) / 256, 256>>>(ei);
    k_rowsortw<<<(N_NODES + WPB - 1) / WPB, NTPB>>>();
    k_scan_block<<<1, 1024>>>(1);
    k_scan_bsums<<<1, 128>>>(1, 1);
    k_scan_add<<<(N_GRAPH + 255) / 256, 256>>>(1);

    int nb_agg  = (N_NODES + WPB - 1) / WPB;                 // warp per node
    int nb_blk  = (N_NODES + WPB * NPW - 1) / (WPB * NPW);   // 8 nodes per warp
    int nb_edge = (N_EDGES + 255) / 256;

    k_node1<<<nb_blk, NTPB>>>(x, emb, lng, lnb, W1, as1, ad1);
    k_elog<<<nb_edge, 256>>>();
    k_agg<<<nb_agg, NTPB>>>(b1, nullptr, 1);
    k_node2<<<nb_blk, NTPB, node2_smem>>>(W2, as2, ad2);
    k_elog<<<nb_edge, 256>>>();
    k_agg<<<nb_agg, NTPB>>>(b2, out, 2);
    k_gate<<<nb_blk, NTPB, gate_smem>>>(out, gw1, gb1, gw2, gb2);
    k_pool<<<N_GRAPH, 128>>>(out, zout);
}

// round 6
// speedup vs baseline: 1.6711x; 1.0759x over previous
#include <cuda_runtime.h>
#include <cuda_fp16.h>

#define N_NODES 100000
#define N_EDGES 1600000
#define N_GRAPH 1024
#define EMB 32
#define DC 128
#define WPB 8       // warps per block
#define NPW 8       // nodes per warp (register blocking in dense kernels)
#define NTPB 256

// ---------------- scratch (static device globals; no allocation) ----------------
__device__ int    g_deg[N_NODES];
__device__ int    g_rowptr[N_NODES + 1];
__device__ int    g_cursor[N_NODES];
__device__ int    g_col[N_EDGES];
__device__ int    g_dst[N_EDGES];
__device__ int    g_bsums[256];
__device__ int    g_gdeg[N_GRAPH];
__device__ int    g_gptr[N_GRAPH + 1];
__device__ __half g_xwh[(size_t)N_NODES * DC];   // fp16 message payload (gathered per edge)
__device__ float  g_h1[(size_t)N_NODES * DC];
__device__ float  g_als[N_NODES * 2];
__device__ float  g_ald[N_NODES * 2];
__device__ float  g_elog[(size_t)N_EDGES * 2];
__device__ float  g_gate[N_NODES];

__device__ __forceinline__ float lrelu(float x, float s) { return x > 0.f ? x : s * x; }

// f32x2 packed helpers (sm_103a; ptxas never emits FFMA2 from C++)
__device__ __forceinline__ unsigned long long pack2(float v) {
    unsigned long long r; asm("mov.b64 %0,{%1,%1};" : "=l"(r) : "f"(v)); return r;
}
__device__ __forceinline__ void fma2(unsigned long long& a, unsigned long long x, unsigned long long p) {
    asm("fma.rn.f32x2 %0,%1,%2,%0;" : "+l"(a) : "l"(x), "l"(p));
}
__device__ __forceinline__ float2 unpack2(unsigned long long v) {
    float2 r; asm("mov.b64 {%0,%1},%2;" : "=f"(r.x), "=f"(r.y) : "l"(v)); return r;
}

// store 4 fp32 as 4 fp16 in one 8B write
__device__ __forceinline__ void store_h4(__half* row, int lane, float a, float b, float c, float d) {
    union { uint2 u; __half2 h[2]; } cv;
    cv.h[0] = __float22half2_rn(make_float2(a, b));
    cv.h[1] = __float22half2_rn(make_float2(c, d));
    ((uint2*)row)[lane] = cv.u;
}

// ---------------- CSR build ----------------
__global__ void k_zero() {
    int i = blockIdx.x * blockDim.x + threadIdx.x;
    if (i < N_NODES) g_deg[i] = 0;
    if (i < N_GRAPH) g_gdeg[i] = 0;
}

__global__ void k_hist(const int* __restrict__ ei, const int* __restrict__ batch) {
    int i = blockIdx.x * blockDim.x + threadIdx.x;
    if (i < N_EDGES) atomicAdd(&g_deg[ei[N_EDGES + i]], 1);
    if (i < N_NODES) atomicAdd(&g_gdeg[batch[i]], 1);
}

__global__ void k_scan_block() {
    __shared__ int sh[1024];
    int t = threadIdx.x;
    int i = blockIdx.x * 1024 + t;
    int v = (i < N_NODES) ? g_deg[i] : 0;
    sh[t] = v;
    __syncthreads();
    for (int off = 1; off < 1024; off <<= 1) {
        int a = (t >= off) ? sh[t - off] : 0;
        __syncthreads();
        sh[t] += a;
        __syncthreads();
    }
    if (i < N_NODES) g_rowptr[i] = sh[t] - v;          // exclusive within block
    if (t == 1023) g_bsums[blockIdx.x] = sh[1023];
}

// fused: per-block redundant scan of block sums + add + cursor init + total
__global__ void k_scan_add2(int nb) {
    __shared__ int sb[128];
    int t = threadIdx.x;
    if (t < 128) sb[t] = (t < nb) ? g_bsums[t] : 0;
    __syncthreads();
    for (int off = 1; off < 128; off <<= 1) {
        int a = (t < 128 && t >= off) ? sb[t - off] : 0;
        __syncthreads();
        if (t < 128) sb[t] += a;
        __syncthreads();
    }
    int i = blockIdx.x * blockDim.x + t;
    if (i < N_NODES) {
        int b = i >> 10;
        int vv = g_rowptr[i] + (b ? sb[b - 1] : 0);
        g_rowptr[i] = vv;
        g_cursor[i] = vv;
    }
    if (i == 0) g_rowptr[N_NODES] = sb[nb - 1];
}

__global__ void k_scatter(const int* __restrict__ ei) {
    int i = blockIdx.x * blockDim.x + threadIdx.x;
    if (i >= N_EDGES) return;
    int s = ei[i];
    int d = ei[N_EDGES + i];
    int pos = atomicAdd(&g_cursor[d], 1);
    g_col[pos] = s;
    g_dst[pos] = d;
}

// warp-per-node smem odd-even sort (deterministic edge order + gather locality)
__global__ void k_rowsortw() {
    __shared__ int buf[WPB][160];
    int wl = threadIdx.x >> 5, lane = threadIdx.x & 31;
    int n = blockIdx.x * WPB + wl;
    if (n >= N_NODES) return;
    int rs = g_rowptr[n], L = g_rowptr[n + 1] - rs;
    if (L <= 1) return;
    if (L <= 160) {
        for (int i = lane; i < L; i += 32) buf[wl][i] = g_col[rs + i];
        __syncwarp();
        for (int p = 0; p < L; p++) {
            for (int i = (p & 1) + 2 * lane; i + 1 < L; i += 64) {
                int a = buf[wl][i], b = buf[wl][i + 1];
                if (a > b) { buf[wl][i] = b; buf[wl][i + 1] = a; }
            }
            __syncwarp();
        }
        for (int i = lane; i < L; i += 32) g_col[rs + i] = buf[wl][i];
    } else if (lane == 0) {
        int re = rs + L;
        for (int i = rs + 1; i < re; i++) {
            int key = g_col[i];
            int j = i - 1;
            while (j >= rs && g_col[j] > key) { g_col[j + 1] = g_col[j]; j--; }
            g_col[j + 1] = key;
        }
    }
}

// single-block graph-pointer scan (N_GRAPH = 1024 exactly)
__global__ void k_gscan() {
    __shared__ int sh[N_GRAPH];
    int t = threadIdx.x;
    int v = g_gdeg[t];
    sh[t] = v;
    __syncthreads();
    for (int off = 1; off < N_GRAPH; off <<= 1) {
        int a = (t >= off) ? sh[t - off] : 0;
        __syncthreads();
        sh[t] += a;
        __syncthreads();
    }
    g_gptr[t] = sh[t] - v;
    if (t == N_GRAPH - 1) g_gptr[N_GRAPH] = sh[t];
}

// ---------------- layer 1: embed + LN + W1 + logits (8 nodes/warp, f32x2) ----------------
__global__ void k_node1(const int* __restrict__ x, const float* __restrict__ emb,
                        const float* __restrict__ lng, const float* __restrict__ lnb,
                        const float* __restrict__ W1, const float* __restrict__ asr,
                        const float* __restrict__ adt) {
    __shared__ ulonglong2 sW[EMB * 32];          // 16KB: W1 [k][lane] as 4 floats
    __shared__ float sxn[WPB][NPW][EMB];         // 8KB
    int tid = threadIdx.x;
    int wl = tid >> 5, lane = tid & 31;
    {
        const ulonglong2* W4 = (const ulonglong2*)W1;
        for (int i = tid; i < EMB * 32; i += NTPB) sW[i] = W4[i];
    }
    int nbase = (blockIdx.x * WPB + wl) * NPW;

    // stage A: LayerNorm rows
#pragma unroll
    for (int j = 0; j < NPW; j++) {
        int n = nbase + j;
        float xn = 0.f;
        if (n < N_NODES) {
            int vi = x[n];
            float xv = emb[vi * EMB + lane];
            float m = xv;
            for (int o = 16; o; o >>= 1) m += __shfl_xor_sync(~0u, m, o);
            m *= (1.f / EMB);
            float dv = xv - m;
            float var = dv * dv;
            for (int o = 16; o; o >>= 1) var += __shfl_xor_sync(~0u, var, o);
            var *= (1.f / EMB);
            xn = dv * rsqrtf(var + 1e-5f) * lng[lane] + lnb[lane];
        }
        sxn[wl][j][lane] = xn;
    }
    __syncthreads();

    // stage B: blocked matmul
    unsigned long long accA[NPW], accB[NPW];
#pragma unroll
    for (int j = 0; j < NPW; j++) { accA[j] = 0ull; accB[j] = 0ull; }
#pragma unroll
    for (int k = 0; k < EMB; k += 4) {
        ulonglong2 w0 = sW[(k + 0) * 32 + lane];
        ulonglong2 w1 = sW[(k + 1) * 32 + lane];
        ulonglong2 w2 = sW[(k + 2) * 32 + lane];
        ulonglong2 w3 = sW[(k + 3) * 32 + lane];
#pragma unroll
        for (int j = 0; j < NPW; j++) {
            float4 h4 = *(const float4*)&sxn[wl][j][k];
            unsigned long long p;
            p = pack2(h4.x); fma2(accA[j], w0.x, p); fma2(accB[j], w0.y, p);
            p = pack2(h4.y); fma2(accA[j], w1.x, p); fma2(accB[j], w1.y, p);
            p = pack2(h4.z); fma2(accA[j], w2.x, p); fma2(accB[j], w2.y, p);
            p = pack2(h4.w); fma2(accA[j], w3.x, p); fma2(accB[j], w3.y, p);
        }
    }

    float4 as4 = __ldg((const float4*)asr + lane);
    float4 ad4 = __ldg((const float4*)adt + lane);
#pragma unroll
    for (int j = 0; j < NPW; j++) {
        int n = nbase + j;
        float2 lo = unpack2(accA[j]), hi = unpack2(accB[j]);
        float ps = lo.x * as4.x + lo.y * as4.y + hi.x * as4.z + hi.y * as4.w;
        float pd = lo.x * ad4.x + lo.y * ad4.y + hi.x * ad4.z + hi.y * ad4.w;
        for (int o = 8; o; o >>= 1) {
            ps += __shfl_xor_sync(~0u, ps, o);
            pd += __shfl_xor_sync(~0u, pd, o);
        }
        if (n < N_NODES) {
            store_h4(g_xwh + (size_t)n * DC, lane, lo.x, lo.y, hi.x, hi.y);
            if ((lane & 15) == 0) {
                int h = lane >> 4;
                g_als[n * 2 + h] = ps;
                g_ald[n * 2 + h] = pd;
            }
        }
    }
}

// ---------------- edge-parallel logit precompute ----------------
__global__ void k_elog() {
    int p = blockIdx.x * blockDim.x + threadIdx.x;
    if (p >= N_EDGES) return;
    int s = g_col[p], d = g_dst[p];
    float2 a = *(const float2*)&g_als[2 * s];
    float2 b = *(const float2*)&g_ald[2 * d];
    ((float2*)g_elog)[p] = make_float2(lrelu(a.x + b.x, 0.2f), lrelu(a.y + b.y, 0.2f));
}

// ---------------- GAT aggregation: warp/node, fused online (m,s) + fp16 gather ----------------
__global__ void k_agg(const float* __restrict__ bias, float* __restrict__ out2, int layer) {
    int n = blockIdx.x * WPB + (threadIdx.x >> 5);
    int lane = threadIdx.x & 31;
    if (n >= N_NODES) return;
    int head = lane >> 4, sub = lane & 15;

    int rs = g_rowptr[n], re = g_rowptr[n + 1];
    float2 a = *(const float2*)&g_als[2 * n];
    float2 b = *(const float2*)&g_ald[2 * n];
    float eself = head ? lrelu(a.y + b.y, 0.2f) : lrelu(a.x + b.x, 0.2f);

    // pass 1: fused online (max, sum) per head; self seeded in lane sub==0 only
    float m, s;
    if (sub == 0) { m = eself; s = 1.f; } else { m = -3.4e38f; s = 0.f; }
    for (int k = rs + sub; k < re; k += 16) {
        float2 e2 = __ldg((const float2*)g_elog + k);
        float e = head ? e2.y : e2.x;
        float mn = fmaxf(m, e);
        s = s * __expf(m - mn) + __expf(e - mn);
        m = mn;
    }
#pragma unroll
    for (int o = 8; o; o >>= 1) {
        float mo = __shfl_xor_sync(~0u, m, o);
        float so = __shfl_xor_sync(~0u, s, o);
        float mn = fmaxf(m, mo);
        s = s * __expf(m - mn) + so * __expf(mo - mn);
        m = mn;
    }
    float inv = 1.f / s;

    // pass 2: weighted fp16 feature accumulation (fp32 accumulators)
    float4 acc;
    {
        float pself = __expf(eself - m);
        uint2 xs = __ldg((const uint2*)(g_xwh + (size_t)n * DC) + lane);
        union { unsigned u; __half2 h; } c0, c1;
        c0.u = xs.x; c1.u = xs.y;
        float2 f01 = __half22float2(c0.h);
        float2 f23 = __half22float2(c1.h);
        acc.x = f01.x * pself; acc.y = f01.y * pself;
        acc.z = f23.x * pself; acc.w = f23.y * pself;
    }
#pragma unroll 8
    for (int k = rs; k < re; k++) {
        int src = __ldg(g_col + k);
        float2 e2 = __ldg((const float2*)g_elog + k);
        float p = __expf((head ? e2.y : e2.x) - m);
        uint2 xv = __ldg((const uint2*)(g_xwh + (size_t)src * DC) + lane);
        union { unsigned u; __half2 h; } c0, c1;
        c0.u = xv.x; c1.u = xv.y;
        float2 f01 = __half22float2(c0.h);
        float2 f23 = __half22float2(c1.h);
        acc.x += f01.x * p; acc.y += f01.y * p;
        acc.z += f23.x * p; acc.w += f23.y * p;
    }

    float4 bi = __ldg((const float4*)bias + lane);
    float4 o;
    o.x = acc.x * inv + bi.x;
    o.y = acc.y * inv + bi.y;
    o.z = acc.z * inv + bi.z;
    o.w = acc.w * inv + bi.w;
    if (layer == 1) {
        o.x = lrelu(o.x, 0.05f); o.y = lrelu(o.y, 0.05f);
        o.z = lrelu(o.z, 0.05f); o.w = lrelu(o.w, 0.05f);
        ((float4*)g_h1)[(size_t)n * 32 + lane] = o;
    } else {
        ((float4*)out2)[(size_t)n * 32 + lane] = o;
    }
}

// ---------------- layer 2 node transform: h1 @ W2 + logits (8 nodes/warp, smem W2) ----------------
__global__ void k_node2(const float* __restrict__ W2, const float* __restrict__ asr,
                        const float* __restrict__ adt) {
    extern __shared__ float dsm[];
    ulonglong2* sW = (ulonglong2*)dsm;                 // DC*32 entries = 64KB
    float* sh = dsm + DC * DC;                         // WPB*NPW*DC floats = 16KB
    int tid = threadIdx.x;
    int wl = tid >> 5, lane = tid & 31;
    {
        const ulonglong2* W4 = (const ulonglong2*)W2;
        for (int i = tid; i < DC * 32; i += NTPB) sW[i] = W4[i];
    }
    int nbase = (blockIdx.x * WPB + wl) * NPW;
    float* shw = sh + (size_t)wl * NPW * DC;
#pragma unroll
    for (int j = 0; j < NPW; j++) {
        int n = nbase + j;
        float4 v = (n < N_NODES) ? ((const float4*)g_h1)[(size_t)n * 32 + lane]
                                 : make_float4(0.f, 0.f, 0.f, 0.f);
        *(float4*)&shw[j * DC + lane * 4] = v;
    }
    __syncthreads();

    unsigned long long accA[NPW], accB[NPW];
#pragma unroll
    for (int j = 0; j < NPW; j++) { accA[j] = 0ull; accB[j] = 0ull; }
    for (int k = 0; k < DC; k += 4) {
        ulonglong2 w0 = sW[(k + 0) * 32 + lane];
        ulonglong2 w1 = sW[(k + 1) * 32 + lane];
        ulonglong2 w2 = sW[(k + 2) * 32 + lane];
        ulonglong2 w3 = sW[(k + 3) * 32 + lane];
#pragma unroll
        for (int j = 0; j < NPW; j++) {
            float4 h4 = *(const float4*)&shw[j * DC + k];
            unsigned long long p;
            p = pack2(h4.x); fma2(accA[j], w0.x, p); fma2(accB[j], w0.y, p);
            p = pack2(h4.y); fma2(accA[j], w1.x, p); fma2(accB[j], w1.y, p);
            p = pack2(h4.z); fma2(accA[j], w2.x, p); fma2(accB[j], w2.y, p);
            p = pack2(h4.w); fma2(accA[j], w3.x, p); fma2(accB[j], w3.y, p);
        }
    }

    float4 as4 = __ldg((const float4*)asr + lane);
    float4 ad4 = __ldg((const float4*)adt + lane);
#pragma unroll
    for (int j = 0; j < NPW; j++) {
        int n = nbase + j;
        float2 lo = unpack2(accA[j]), hi = unpack2(accB[j]);
        float ps = lo.x * as4.x + lo.y * as4.y + hi.x * as4.z + hi.y * as4.w;
        float pd = lo.x * ad4.x + lo.y * ad4.y + hi.x * ad4.z + hi.y * ad4.w;
        for (int o = 8; o; o >>= 1) {
            ps += __shfl_xor_sync(~0u, ps, o);
            pd += __shfl_xor_sync(~0u, pd, o);
        }
        if (n < N_NODES) {
            store_h4(g_xwh + (size_t)n * DC, lane, lo.x, lo.y, hi.x, hi.y);
            if ((lane & 15) == 0) {
                int h = lane >> 4;
                g_als[n * 2 + h] = ps;
                g_ald[n * 2 + h] = pd;
            }
        }
    }
}

// ---------------- gate MLP (8 nodes/warp, smem gw1) ----------------
__global__ void k_gate(const float* __restrict__ hout, const float* __restrict__ gw1,
                       const float* __restrict__ gb1, const float* __restrict__ gw2,
                       const float* __restrict__ gb2) {
    extern __shared__ float dsm[];
    unsigned long long* sg = (unsigned long long*)dsm;   // DC*32 float2 pairs, 32KB
    float* sh = dsm + DC * 64;                           // stage 16KB
    int tid = threadIdx.x;
    int wl = tid >> 5, lane = tid & 31;
    {
        const unsigned long long* G = (const unsigned long long*)gw1;
        for (int i = tid; i < DC * 32; i += NTPB) sg[i] = G[i];
    }
    int nbase = (blockIdx.x * WPB + wl) * NPW;
    float* shw = sh + (size_t)wl * NPW * DC;
#pragma unroll
    for (int j = 0; j < NPW; j++) {
        int n = nbase + j;
        float4 v = (n < N_NODES) ? ((const float4*)hout)[(size_t)n * 32 + lane]
                                 : make_float4(0.f, 0.f, 0.f, 0.f);
        *(float4*)&shw[j * DC + lane * 4] = v;
    }
    __syncthreads();

    unsigned long long acc[NPW];
#pragma unroll
    for (int j = 0; j < NPW; j++) acc[j] = 0ull;
    for (int k = 0; k < DC; k += 4) {
        unsigned long long w0 = sg[(k + 0) * 32 + lane];
        unsigned long long w1 = sg[(k + 1) * 32 + lane];
        unsigned long long w2 = sg[(k + 2) * 32 + lane];
        unsigned long long w3 = sg[(k + 3) * 32 + lane];
#pragma unroll
        for (int j = 0; j < NPW; j++) {
            float4 h4 = *(const float4*)&shw[j * DC + k];
            fma2(acc[j], w0, pack2(h4.x));
            fma2(acc[j], w1, pack2(h4.y));
            fma2(acc[j], w2, pack2(h4.z));
            fma2(acc[j], w3, pack2(h4.w));
        }
    }

    float2 gb = __ldg((const float2*)gb1 + lane);
    float2 g2 = __ldg((const float2*)gw2 + lane);
    float gbias = __ldg(gb2);
#pragma unroll
    for (int j = 0; j < NPW; j++) {
        float2 u = unpack2(acc[j]);
        u.x = lrelu(u.x + gb.x, 0.05f);
        u.y = lrelu(u.y + gb.y, 0.05f);
        float ps = u.x * g2.x + u.y * g2.y;
        for (int o = 16; o; o >>= 1) ps += __shfl_xor_sync(~0u, ps, o);
        int n = nbase + j;
        if (lane == 0 && n < N_NODES) g_gate[n] = ps + gbias;
    }
}

// ---------------- per-graph softmax pooling ----------------
__global__ void k_pool(const float* __restrict__ hout, float* __restrict__ zout) {
    int g = blockIdx.x;
    int t = threadIdx.x;
    int s = g_gptr[g], e = g_gptr[g + 1];
    __shared__ float red[128];
    __shared__ float wbuf[128];

    float lm = -3.4e38f;
    for (int i = s + t; i < e; i += 128) lm = fmaxf(lm, g_gate[i]);
    red[t] = lm;
    __syncthreads();
    for (int o = 64; o; o >>= 1) { if (t < o) red[t] = fmaxf(red[t], red[t + o]); __syncthreads(); }
    float gm = red[0];
    __syncthreads();

    float ls = 0.f;
    for (int i = s + t; i < e; i += 128) ls += __expf(g_gate[i] - gm);
    red[t] = ls;
    __syncthreads();
    for (int o = 64; o; o >>= 1) { if (t < o) red[t] += red[t + o]; __syncthreads(); }
    float inv = (e > s) ? 1.f / red[0] : 0.f;
    __syncthreads();

    float acc = 0.f;
    for (int base = s; base < e; base += 128) {
        int i = base + t;
        wbuf[t] = (i < e) ? __expf(g_gate[i] - gm) * inv : 0.f;
        __syncthreads();
        int cnt = min(128, e - base);
        for (int j = 0; j < cnt; j++)
            acc += wbuf[j] * hout[(size_t)(base + j) * DC + t];
        __syncthreads();
    }
    zout[g * DC + t] = acc;
}

// ---------------- launch ----------------
extern "C" void kernel_launch(void* const* d_in, const int* in_sizes, int n_in,
                              void* d_out, int out_size) {
    const int*   x     = (const int*)d_in[0];
    const int*   ei    = (const int*)d_in[1];
    const int*   batch = (const int*)d_in[2];
    const float* emb   = (const float*)d_in[3];
    const float* lng   = (const float*)d_in[4];
    const float* lnb   = (const float*)d_in[5];
    const float* W1    = (const float*)d_in[6];
    const float* as1   = (const float*)d_in[7];
    const float* ad1   = (const float*)d_in[8];
    const float* b1    = (const float*)d_in[9];
    const float* W2    = (const float*)d_in[10];
    const float* as2   = (const float*)d_in[11];
    const float* ad2   = (const float*)d_in[12];
    const float* b2    = (const float*)d_in[13];
    const float* gw1   = (const float*)d_in[14];
    const float* gb1   = (const float*)d_in[15];
    const float* gw2   = (const float*)d_in[16];
    const float* gb2   = (const float*)d_in[17];
    float* out  = (float*)d_out;
    float* zout = out + (size_t)N_NODES * DC;

    const int node2_smem = DC * DC * 4 + WPB * NPW * DC * 4;   // 80 KB
    const int gate_smem  = DC * 64 * 4 + WPB * NPW * DC * 4;   // 48 KB
    cudaFuncSetAttribute(k_node2, cudaFuncAttributeMaxDynamicSharedMemorySize, node2_smem);
    cudaFuncSetAttribute(k_gate,  cudaFuncAttributeMaxDynamicSharedMemorySize, gate_smem);

    int nb_scan = (N_NODES + 1023) / 1024;

    // CSR build + graph segment pointers (7 launches)
    k_zero<<<(N_NODES + 255) / 256, 256>>>();
    k_hist<<<(N_EDGES + 255) / 256, 256>>>(ei, batch);
    k_scan_block<<<nb_scan, 1024>>>();
    k_scan_add2<<<(N_NODES + 255) / 256, 256>>>(nb_scan);
    k_scatter<<<(N_EDGES + 255) / 256, 256>>>(ei);
    k_rowsortw<<<(N_NODES + WPB - 1) / WPB, NTPB>>>();
    k_gscan<<<1, N_GRAPH>>>();

    int nb_agg  = (N_NODES + WPB - 1) / WPB;                 // warp per node
    int nb_blk  = (N_NODES + WPB * NPW - 1) / (WPB * NPW);   // 8 nodes per warp
    int nb_edge = (N_EDGES + 255) / 256;

    k_node1<<<nb_blk, NTPB>>>(x, emb, lng, lnb, W1, as1, ad1);
    k_elog<<<nb_edge, 256>>>();
    k_agg<<<nb_agg, NTPB>>>(b1, nullptr, 1);
    k_node2<<<nb_blk, NTPB, node2_smem>>>(W2, as2, ad2);
    k_elog<<<nb_edge, 256>>>();
    k_agg<<<nb_agg, NTPB>>>(b2, out, 2);
    k_gate<<<nb_blk, NTPB, gate_smem>>>(out, gw1, gb1, gw2, gb2);
    k_pool<<<N_GRAPH, 128>>>(out, zout);
}

// round 7
// speedup vs baseline: 1.7262x; 1.0330x over previous
#include <cuda_runtime.h>
#include <cuda_fp16.h>

#define N_NODES 100000
#define N_EDGES 1600000
#define N_GRAPH 1024
#define EMB 32
#define DC 128
#define WPB 8       // warps per block
#define NPW 8       // nodes per warp (register blocking in dense kernels)
#define NTPB 256

// ---------------- scratch (static device globals; no allocation) ----------------
__device__ int    g_deg[N_NODES];
__device__ int    g_rowptr[N_NODES + 1];
__device__ int    g_cursor[N_NODES];
__device__ int    g_col[N_EDGES];
__device__ int    g_dst[N_EDGES];
__device__ int    g_bsums[256];
__device__ int    g_gdeg[N_GRAPH];
__device__ int    g_gptr[N_GRAPH + 1];
__device__ __half g_xwh[(size_t)N_NODES * DC];   // fp16 message payload
__device__ float  g_h1[(size_t)N_NODES * DC];
__device__ float  g_als[N_NODES * 2];
__device__ float  g_ald[N_NODES * 2];
__device__ float  g_elog[(size_t)N_EDGES * 2];
__device__ float  g_gate[N_NODES];

__device__ __forceinline__ float lrelu(float x, float s) { return x > 0.f ? x : s * x; }

// f32x2 packed helpers (sm_103a; ptxas never emits FFMA2 from C++)
__device__ __forceinline__ unsigned long long pack2(float v) {
    unsigned long long r; asm("mov.b64 %0,{%1,%1};" : "=l"(r) : "f"(v)); return r;
}
__device__ __forceinline__ void fma2(unsigned long long& a, unsigned long long x, unsigned long long p) {
    asm("fma.rn.f32x2 %0,%1,%2,%0;" : "+l"(a) : "l"(x), "l"(p));
}
__device__ __forceinline__ float2 unpack2(unsigned long long v) {
    float2 r; asm("mov.b64 {%0,%1},%2;" : "=f"(r.x), "=f"(r.y) : "l"(v)); return r;
}

// store 4 fp32 as 4 fp16 in one 8B write
__device__ __forceinline__ void store_h4(__half* row, int lane, float a, float b, float c, float d) {
    union { uint2 u; __half2 h[2]; } cv;
    cv.h[0] = __float22half2_rn(make_float2(a, b));
    cv.h[1] = __float22half2_rn(make_float2(c, d));
    ((uint2*)row)[lane] = cv.u;
}

// 8 halfs (uint4) * p accumulated into 8 fp32
__device__ __forceinline__ void h8_fma(float* acc, uint4 v, float p) {
    union { unsigned u; __half2 h; } c;
    float2 f;
    c.u = v.x; f = __half22float2(c.h); acc[0] += f.x * p; acc[1] += f.y * p;
    c.u = v.y; f = __half22float2(c.h); acc[2] += f.x * p; acc[3] += f.y * p;
    c.u = v.z; f = __half22float2(c.h); acc[4] += f.x * p; acc[5] += f.y * p;
    c.u = v.w; f = __half22float2(c.h); acc[6] += f.x * p; acc[7] += f.y * p;
}

// ---------------- CSR build ----------------
__global__ void k_zero() {
    int i = blockIdx.x * blockDim.x + threadIdx.x;
    if (i < N_NODES) g_deg[i] = 0;
    if (i < N_GRAPH) g_gdeg[i] = 0;
}

__global__ void k_hist(const int* __restrict__ ei, const int* __restrict__ batch) {
    int i = blockIdx.x * blockDim.x + threadIdx.x;
    if (i < N_EDGES) atomicAdd(&g_deg[ei[N_EDGES + i]], 1);
    if (i < N_NODES) atomicAdd(&g_gdeg[batch[i]], 1);
}

__global__ void k_scan_block() {
    __shared__ int sh[1024];
    int t = threadIdx.x;
    int i = blockIdx.x * 1024 + t;
    int v = (i < N_NODES) ? g_deg[i] : 0;
    sh[t] = v;
    __syncthreads();
    for (int off = 1; off < 1024; off <<= 1) {
        int a = (t >= off) ? sh[t - off] : 0;
        __syncthreads();
        sh[t] += a;
        __syncthreads();
    }
    if (i < N_NODES) g_rowptr[i] = sh[t] - v;
    if (t == 1023) g_bsums[blockIdx.x] = sh[1023];
}

// fused: block-sum scan + add + cursor init + total; last block also builds g_gptr
__global__ void k_scan_add2(int nb) {
    __shared__ int sb[128];
    int t = threadIdx.x;
    if (t < 128) sb[t] = (t < nb) ? g_bsums[t] : 0;
    __syncthreads();
    for (int off = 1; off < 128; off <<= 1) {
        int a = (t < 128 && t >= off) ? sb[t - off] : 0;
        __syncthreads();
        if (t < 128) sb[t] += a;
        __syncthreads();
    }
    int i = blockIdx.x * blockDim.x + t;
    if (i < N_NODES) {
        int b = i >> 10;
        int vv = g_rowptr[i] + (b ? sb[b - 1] : 0);
        g_rowptr[i] = vv;
        g_cursor[i] = vv;
    }
    if (i == 0) g_rowptr[N_NODES] = sb[nb - 1];

    if (blockIdx.x == gridDim.x - 1) {    // graph-pointer scan (1024 entries, 4/thread)
        __shared__ int gs[256];
        int b4 = t * 4;
        int a0 = g_gdeg[b4], a1 = g_gdeg[b4 + 1], a2 = g_gdeg[b4 + 2], a3 = g_gdeg[b4 + 3];
        int tot = a0 + a1 + a2 + a3;
        gs[t] = tot;
        __syncthreads();
        for (int off = 1; off < 256; off <<= 1) {
            int a = (t >= off) ? gs[t - off] : 0;
            __syncthreads();
            gs[t] += a;
            __syncthreads();
        }
        int excl = gs[t] - tot;
        g_gptr[b4]     = excl;
        g_gptr[b4 + 1] = excl + a0;
        g_gptr[b4 + 2] = excl + a0 + a1;
        g_gptr[b4 + 3] = excl + a0 + a1 + a2;
        if (t == 255) g_gptr[N_GRAPH] = gs[255];
    }
}

__global__ void k_scatter(const int* __restrict__ ei) {
    int i = blockIdx.x * blockDim.x + threadIdx.x;
    if (i >= N_EDGES) return;
    int s = ei[i];
    int d = ei[N_EDGES + i];
    int pos = atomicAdd(&g_cursor[d], 1);
    g_col[pos] = s;
    g_dst[pos] = d;
}

// warp-per-node sort: shfl bitonic (L<=32 and L<=64 paths), smem fallback
__global__ void k_rowsortw() {
    __shared__ int buf[WPB][160];
    int wl = threadIdx.x >> 5, lane = threadIdx.x & 31;
    int n = blockIdx.x * WPB + wl;
    if (n >= N_NODES) return;
    int rs = g_rowptr[n], L = g_rowptr[n + 1] - rs;
    if (L <= 1) return;
    if (L <= 32) {
        int v = (lane < L) ? g_col[rs + lane] : 0x7fffffff;
#pragma unroll
        for (int k = 2; k <= 32; k <<= 1) {
#pragma unroll
            for (int j = k >> 1; j; j >>= 1) {
                int o = __shfl_xor_sync(~0u, v, j);
                bool up = ((lane & k) == 0);
                bool lo = ((lane & j) == 0);
                v = (up == lo) ? min(v, o) : max(v, o);
            }
        }
        if (lane < L) g_col[rs + lane] = v;
    } else if (L <= 64) {
        int i0 = lane, i1 = lane + 32;
        int v0 = (i0 < L) ? g_col[rs + i0] : 0x7fffffff;
        int v1 = (i1 < L) ? g_col[rs + i1] : 0x7fffffff;
#pragma unroll
        for (int k = 2; k <= 64; k <<= 1) {
#pragma unroll
            for (int j = k >> 1; j; j >>= 1) {
                if (j >= 32) {   // k=64, j=32: partner across regs, same lane
                    int lo = min(v0, v1), hi = max(v0, v1);
                    v0 = lo; v1 = hi;
                } else {
                    int o0 = __shfl_xor_sync(~0u, v0, j);
                    int o1 = __shfl_xor_sync(~0u, v1, j);
                    bool up0 = ((i0 & k) == 0), up1 = ((i1 & k) == 0);
                    bool lo0 = ((i0 & j) == 0), lo1 = ((i1 & j) == 0);
                    v0 = (up0 == lo0) ? min(v0, o0) : max(v0, o0);
                    v1 = (up1 == lo1) ? min(v1, o1) : max(v1, o1);
                }
            }
        }
        if (i0 < L) g_col[rs + i0] = v0;
        if (i1 < L) g_col[rs + i1] = v1;
    } else if (L <= 160) {
        for (int i = lane; i < L; i += 32) buf[wl][i] = g_col[rs + i];
        __syncwarp();
        for (int p = 0; p < L; p++) {
            for (int i = (p & 1) + 2 * lane; i + 1 < L; i += 64) {
                int a = buf[wl][i], b = buf[wl][i + 1];
                if (a > b) { buf[wl][i] = b; buf[wl][i + 1] = a; }
            }
            __syncwarp();
        }
        for (int i = lane; i < L; i += 32) g_col[rs + i] = buf[wl][i];
    } else if (lane == 0) {
        int re = rs + L;
        for (int i = rs + 1; i < re; i++) {
            int key = g_col[i];
            int j = i - 1;
            while (j >= rs && g_col[j] > key) { g_col[j + 1] = g_col[j]; j--; }
            g_col[j + 1] = key;
        }
    }
}

// ---------------- layer 1: embed + LN + W1 + logits (8 nodes/warp, f32x2) ----------------
__global__ void k_node1(const int* __restrict__ x, const float* __restrict__ emb,
                        const float* __restrict__ lng, const float* __restrict__ lnb,
                        const float* __restrict__ W1, const float* __restrict__ asr,
                        const float* __restrict__ adt) {
    __shared__ ulonglong2 sW[EMB * 32];
    __shared__ float sxn[WPB][NPW][EMB];
    int tid = threadIdx.x;
    int wl = tid >> 5, lane = tid & 31;
    {
        const ulonglong2* W4 = (const ulonglong2*)W1;
        for (int i = tid; i < EMB * 32; i += NTPB) sW[i] = W4[i];
    }
    int nbase = (blockIdx.x * WPB + wl) * NPW;

#pragma unroll
    for (int j = 0; j < NPW; j++) {
        int n = nbase + j;
        float xn = 0.f;
        if (n < N_NODES) {
            int vi = x[n];
            float xv = emb[vi * EMB + lane];
            float m = xv;
            for (int o = 16; o; o >>= 1) m += __shfl_xor_sync(~0u, m, o);
            m *= (1.f / EMB);
            float dv = xv - m;
            float var = dv * dv;
            for (int o = 16; o; o >>= 1) var += __shfl_xor_sync(~0u, var, o);
            var *= (1.f / EMB);
            xn = dv * rsqrtf(var + 1e-5f) * lng[lane] + lnb[lane];
        }
        sxn[wl][j][lane] = xn;
    }
    __syncthreads();

    unsigned long long accA[NPW], accB[NPW];
#pragma unroll
    for (int j = 0; j < NPW; j++) { accA[j] = 0ull; accB[j] = 0ull; }
#pragma unroll
    for (int k = 0; k < EMB; k += 4) {
        ulonglong2 w0 = sW[(k + 0) * 32 + lane];
        ulonglong2 w1 = sW[(k + 1) * 32 + lane];
        ulonglong2 w2 = sW[(k + 2) * 32 + lane];
        ulonglong2 w3 = sW[(k + 3) * 32 + lane];
#pragma unroll
        for (int j = 0; j < NPW; j++) {
            float4 h4 = *(const float4*)&sxn[wl][j][k];
            unsigned long long p;
            p = pack2(h4.x); fma2(accA[j], w0.x, p); fma2(accB[j], w0.y, p);
            p = pack2(h4.y); fma2(accA[j], w1.x, p); fma2(accB[j], w1.y, p);
            p = pack2(h4.z); fma2(accA[j], w2.x, p); fma2(accB[j], w2.y, p);
            p = pack2(h4.w); fma2(accA[j], w3.x, p); fma2(accB[j], w3.y, p);
        }
    }

    float4 as4 = __ldg((const float4*)asr + lane);
    float4 ad4 = __ldg((const float4*)adt + lane);
#pragma unroll
    for (int j = 0; j < NPW; j++) {
        int n = nbase + j;
        float2 lo = unpack2(accA[j]), hi = unpack2(accB[j]);
        float ps = lo.x * as4.x + lo.y * as4.y + hi.x * as4.z + hi.y * as4.w;
        float pd = lo.x * ad4.x + lo.y * ad4.y + hi.x * ad4.z + hi.y * ad4.w;
        for (int o = 8; o; o >>= 1) {
            ps += __shfl_xor_sync(~0u, ps, o);
            pd += __shfl_xor_sync(~0u, pd, o);
        }
        if (n < N_NODES) {
            store_h4(g_xwh + (size_t)n * DC, lane, lo.x, lo.y, hi.x, hi.y);
            if ((lane & 15) == 0) {
                int h = lane >> 4;
                g_als[n * 2 + h] = ps;
                g_ald[n * 2 + h] = pd;
            }
        }
    }
}

// ---------------- edge-parallel logit precompute ----------------
__global__ void k_elog() {
    int p = blockIdx.x * blockDim.x + threadIdx.x;
    if (p >= N_EDGES) return;
    int s = g_col[p], d = g_dst[p];
    float2 a = *(const float2*)&g_als[2 * s];
    float2 b = *(const float2*)&g_ald[2 * d];
    ((float2*)g_elog)[p] = make_float2(lrelu(a.x + b.x, 0.2f), lrelu(a.y + b.y, 0.2f));
}

// ---------------- GAT aggregation: warp/node, 2 edges/iter, no-max softmax ----------------
__global__ void k_agg(const float* __restrict__ bias, float* __restrict__ out2, int layer) {
    int n = blockIdx.x * WPB + (threadIdx.x >> 5);
    int lane = threadIdx.x & 31;
    if (n >= N_NODES) return;

    int rs = g_rowptr[n], re = g_rowptr[n + 1];
    float2 a = *(const float2*)&g_als[2 * n];
    float2 b = *(const float2*)&g_ald[2 * n];
    float es0 = lrelu(a.x + b.x, 0.2f);
    float es1 = lrelu(a.y + b.y, 0.2f);

    // pass 1: plain sum of exp per head (logits bounded; exact-math equal to max-shifted)
    float s0 = 0.f, s1 = 0.f;
    for (int k = rs + lane; k < re; k += 32) {
        float2 e2 = __ldg((const float2*)g_elog + k);
        s0 += __expf(e2.x);
        s1 += __expf(e2.y);
    }
#pragma unroll
    for (int o = 16; o; o >>= 1) {
        s0 += __shfl_xor_sync(~0u, s0, o);
        s1 += __shfl_xor_sync(~0u, s1, o);
    }
    float ps0 = __expf(es0), ps1 = __expf(es1);
    float inv0 = 1.f / (s0 + ps0);
    float inv1 = 1.f / (s1 + ps1);

    int half  = lane >> 4;   // edge slot within iteration
    int s16   = lane & 15;   // feature chunk: 8 halfs [8*s16, 8*s16+8)
    int headb = s16 >> 3;    // head owning my dims

    // pass 2: weighted gather, 2 edges per warp iteration, uint4 (8 halfs) per lane
    float acc[8];
    {
        float pself = (half == 0) ? (headb ? ps1 : ps0) : 0.f;
        uint4 xs = __ldg((const uint4*)(g_xwh + (size_t)n * DC) + s16);
#pragma unroll
        for (int i = 0; i < 8; i++) acc[i] = 0.f;
        h8_fma(acc, xs, pself);
    }
#pragma unroll 4
    for (int k = rs; k < re; k += 2) {
        int kk = k + half;
        int kc = kk < re ? kk : re - 1;
        int src = __ldg(g_col + kc);
        float2 e2 = __ldg((const float2*)g_elog + kc);
        float e = headb ? e2.y : e2.x;
        float p = (kk < re) ? __expf(e) : 0.f;
        uint4 xv = __ldg((const uint4*)(g_xwh + (size_t)src * DC) + s16);
        h8_fma(acc, xv, p);
    }
    // combine the two edge slots
#pragma unroll
    for (int i = 0; i < 8; i++) acc[i] += __shfl_xor_sync(~0u, acc[i], 16);

    float invh = headb ? inv1 : inv0;
    int idx = s16 * 2 + half;            // which float4 of the 32 this lane writes
    float4 bi = __ldg((const float4*)bias + idx);
    const float* ap = acc + half * 4;
    float4 o;
    o.x = ap[0] * invh + bi.x;
    o.y = ap[1] * invh + bi.y;
    o.z = ap[2] * invh + bi.z;
    o.w = ap[3] * invh + bi.w;
    if (layer == 1) {
        o.x = lrelu(o.x, 0.05f); o.y = lrelu(o.y, 0.05f);
        o.z = lrelu(o.z, 0.05f); o.w = lrelu(o.w, 0.05f);
        ((float4*)g_h1)[(size_t)n * 32 + idx] = o;
    } else {
        ((float4*)out2)[(size_t)n * 32 + idx] = o;
    }
}

// ---------------- layer 2 node transform: h1 @ W2 + logits (8 nodes/warp, smem W2) ----------------
__global__ void k_node2(const float* __restrict__ W2, const float* __restrict__ asr,
                        const float* __restrict__ adt) {
    extern __shared__ float dsm[];
    ulonglong2* sW = (ulonglong2*)dsm;                 // 64KB
    float* sh = dsm + DC * DC;                         // 16KB
    int tid = threadIdx.x;
    int wl = tid >> 5, lane = tid & 31;
    {
        const ulonglong2* W4 = (const ulonglong2*)W2;
        for (int i = tid; i < DC * 32; i += NTPB) sW[i] = W4[i];
    }
    int nbase = (blockIdx.x * WPB + wl) * NPW;
    float* shw = sh + (size_t)wl * NPW * DC;
#pragma unroll
    for (int j = 0; j < NPW; j++) {
        int n = nbase + j;
        float4 v = (n < N_NODES) ? ((const float4*)g_h1)[(size_t)n * 32 + lane]
                                 : make_float4(0.f, 0.f, 0.f, 0.f);
        *(float4*)&shw[j * DC + lane * 4] = v;
    }
    __syncthreads();

    unsigned long long accA[NPW], accB[NPW];
#pragma unroll
    for (int j = 0; j < NPW; j++) { accA[j] = 0ull; accB[j] = 0ull; }
    for (int k = 0; k < DC; k += 4) {
        ulonglong2 w0 = sW[(k + 0) * 32 + lane];
        ulonglong2 w1 = sW[(k + 1) * 32 + lane];
        ulonglong2 w2 = sW[(k + 2) * 32 + lane];
        ulonglong2 w3 = sW[(k + 3) * 32 + lane];
#pragma unroll
        for (int j = 0; j < NPW; j++) {
            float4 h4 = *(const float4*)&shw[j * DC + k];
            unsigned long long p;
            p = pack2(h4.x); fma2(accA[j], w0.x, p); fma2(accB[j], w0.y, p);
            p = pack2(h4.y); fma2(accA[j], w1.x, p); fma2(accB[j], w1.y, p);
            p = pack2(h4.z); fma2(accA[j], w2.x, p); fma2(accB[j], w2.y, p);
            p = pack2(h4.w); fma2(accA[j], w3.x, p); fma2(accB[j], w3.y, p);
        }
    }

    float4 as4 = __ldg((const float4*)asr + lane);
    float4 ad4 = __ldg((const float4*)adt + lane);
#pragma unroll
    for (int j = 0; j < NPW; j++) {
        int n = nbase + j;
        float2 lo = unpack2(accA[j]), hi = unpack2(accB[j]);
        float ps = lo.x * as4.x + lo.y * as4.y + hi.x * as4.z + hi.y * as4.w;
        float pd = lo.x * ad4.x + lo.y * ad4.y + hi.x * ad4.z + hi.y * ad4.w;
        for (int o = 8; o; o >>= 1) {
            ps += __shfl_xor_sync(~0u, ps, o);
            pd += __shfl_xor_sync(~0u, pd, o);
        }
        if (n < N_NODES) {
            store_h4(g_xwh + (size_t)n * DC, lane, lo.x, lo.y, hi.x, hi.y);
            if ((lane & 15) == 0) {
                int h = lane >> 4;
                g_als[n * 2 + h] = ps;
                g_ald[n * 2 + h] = pd;
            }
        }
    }
}

// ---------------- gate MLP (8 nodes/warp, smem gw1) ----------------
__global__ void k_gate(const float* __restrict__ hout, const float* __restrict__ gw1,
                       const float* __restrict__ gb1, const float* __restrict__ gw2,
                       const float* __restrict__ gb2) {
    extern __shared__ float dsm[];
    unsigned long long* sg = (unsigned long long*)dsm;   // 32KB
    float* sh = dsm + DC * 64;                           // 16KB
    int tid = threadIdx.x;
    int wl = tid >> 5, lane = tid & 31;
    {
        const unsigned long long* G = (const unsigned long long*)gw1;
        for (int i = tid; i < DC * 32; i += NTPB) sg[i] = G[i];
    }
    int nbase = (blockIdx.x * WPB + wl) * NPW;
    float* shw = sh + (size_t)wl * NPW * DC;
#pragma unroll
    for (int j = 0; j < NPW; j++) {
        int n = nbase + j;
        float4 v = (n < N_NODES) ? ((const float4*)hout)[(size_t)n * 32 + lane]
                                 : make_float4(0.f, 0.f, 0.f, 0.f);
        *(float4*)&shw[j * DC + lane * 4] = v;
    }
    __syncthreads();

    unsigned long long acc[NPW];
#pragma unroll
    for (int j = 0; j < NPW; j++) acc[j] = 0ull;
    for (int k = 0; k < DC; k += 4) {
        unsigned long long w0 = sg[(k + 0) * 32 + lane];
        unsigned long long w1 = sg[(k + 1) * 32 + lane];
        unsigned long long w2 = sg[(k + 2) * 32 + lane];
        unsigned long long w3 = sg[(k + 3) * 32 + lane];
#pragma unroll
        for (int j = 0; j < NPW; j++) {
            float4 h4 = *(const float4*)&shw[j * DC + k];
            fma2(acc[j], w0, pack2(h4.x));
            fma2(acc[j], w1, pack2(h4.y));
            fma2(acc[j], w2, pack2(h4.z));
            fma2(acc[j], w3, pack2(h4.w));
        }
    }

    float2 gb = __ldg((const float2*)gb1 + lane);
    float2 g2 = __ldg((const float2*)gw2 + lane);
    float gbias = __ldg(gb2);
#pragma unroll
    for (int j = 0; j < NPW; j++) {
        float2 u = unpack2(acc[j]);
        u.x = lrelu(u.x + gb.x, 0.05f);
        u.y = lrelu(u.y + gb.y, 0.05f);
        float ps = u.x * g2.x + u.y * g2.y;
        for (int o = 16; o; o >>= 1) ps += __shfl_xor_sync(~0u, ps, o);
        int n = nbase + j;
        if (lane == 0 && n < N_NODES) g_gate[n] = ps + gbias;
    }
}

// ---------------- per-graph softmax pooling ----------------
__global__ void k_pool(const float* __restrict__ hout, float* __restrict__ zout) {
    int g = blockIdx.x;
    int t = threadIdx.x;
    int s = g_gptr[g], e = g_gptr[g + 1];
    __shared__ float red[128];
    __shared__ float wbuf[128];

    float lm = -3.4e38f;
    for (int i = s + t; i < e; i += 128) lm = fmaxf(lm, g_gate[i]);
    red[t] = lm;
    __syncthreads();
    for (int o = 64; o; o >>= 1) { if (t < o) red[t] = fmaxf(red[t], red[t + o]); __syncthreads(); }
    float gm = red[0];
    __syncthreads();

    float ls = 0.f;
    for (int i = s + t; i < e; i += 128) ls += __expf(g_gate[i] - gm);
    red[t] = ls;
    __syncthreads();
    for (int o = 64; o; o >>= 1) { if (t < o) red[t] += red[t + o]; __syncthreads(); }
    float inv = (e > s) ? 1.f / red[0] : 0.f;
    __syncthreads();

    float acc = 0.f;
    for (int base = s; base < e; base += 128) {
        int i = base + t;
        wbuf[t] = (i < e) ? __expf(g_gate[i] - gm) * inv : 0.f;
        __syncthreads();
        int cnt = min(128, e - base);
#pragma unroll 4
        for (int j = 0; j < cnt; j++)
            acc += wbuf[j] * hout[(size_t)(base + j) * DC + t];
        __syncthreads();
    }
    zout[g * DC + t] = acc;
}

// ---------------- launch ----------------
extern "C" void kernel_launch(void* const* d_in, const int* in_sizes, int n_in,
                              void* d_out, int out_size) {
    const int*   x     = (const int*)d_in[0];
    const int*   ei    = (const int*)d_in[1];
    const int*   batch = (const int*)d_in[2];
    const float* emb   = (const float*)d_in[3];
    const float* lng   = (const float*)d_in[4];
    const float* lnb   = (const float*)d_in[5];
    const float* W1    = (const float*)d_in[6];
    const float* as1   = (const float*)d_in[7];
    const float* ad1   = (const float*)d_in[8];
    const float* b1    = (const float*)d_in[9];
    const float* W2    = (const float*)d_in[10];
    const float* as2   = (const float*)d_in[11];
    const float* ad2   = (const float*)d_in[12];
    const float* b2    = (const float*)d_in[13];
    const float* gw1   = (const float*)d_in[14];
    const float* gb1   = (const float*)d_in[15];
    const float* gw2   = (const float*)d_in[16];
    const float* gb2   = (const float*)d_in[17];
    float* out  = (float*)d_out;
    float* zout = out + (size_t)N_NODES * DC;

    const int node2_smem = DC * DC * 4 + WPB * NPW * DC * 4;   // 80 KB
    const int gate_smem  = DC * 64 * 4 + WPB * NPW * DC * 4;   // 48 KB
    cudaFuncSetAttribute(k_node2, cudaFuncAttributeMaxDynamicSharedMemorySize, node2_smem);
    cudaFuncSetAttribute(k_gate,  cudaFuncAttributeMaxDynamicSharedMemorySize, gate_smem);

    int nb_scan = (N_NODES + 1023) / 1024;

    // CSR build + graph segment pointers (6 launches)
    k_zero<<<(N_NODES + 255) / 256, 256>>>();
    k_hist<<<(N_EDGES + 255) / 256, 256>>>(ei, batch);
    k_scan_block<<<nb_scan, 1024>>>();
    k_scan_add2<<<(N_NODES + 255) / 256, 256>>>(nb_scan);
    k_scatter<<<(N_EDGES + 255) / 256, 256>>>(ei);
    k_rowsortw<<<(N_NODES + WPB - 1) / WPB, NTPB>>>();

    int nb_agg  = (N_NODES + WPB - 1) / WPB;
    int nb_blk  = (N_NODES + WPB * NPW - 1) / (WPB * NPW);
    int nb_edge = (N_EDGES + 255) / 256;

    k_node1<<<nb_blk, NTPB>>>(x, emb, lng, lnb, W1, as1, ad1);
    k_elog<<<nb_edge, 256>>>();
    k_agg<<<nb_agg, NTPB>>>(b1, nullptr, 1);
    k_node2<<<nb_blk, NTPB, node2_smem>>>(W2, as2, ad2);
    k_elog<<<nb_edge, 256>>>();
    k_agg<<<nb_agg, NTPB>>>(b2, out, 2);
    k_gate<<<nb_blk, NTPB, gate_smem>>>(out, gw1, gb1, gw2, gb2);
    k_pool<<<N_GRAPH, 128>>>(out, zout);
}